// round 14
// baseline (speedup 1.0000x reference)
#include <cuda_runtime.h>
#include <math.h>
#include <stdint.h>

#define B_ 16
#define C_ 64
#define H_ 192
#define W_ 192
#define R_ 64

// ---------------- scratch (device globals; no allocation) ----------------
__device__ float g_cp[B_ * C_];            // [B][C]
__device__ float g_hp[B_ * H_];            // [B][H]
__device__ float g_wp[B_ * W_];            // [B][W]
__device__ float g_RS[B_ * C_ * H_];       // per-plane row sums  [B][C][H]
__device__ float g_CS[B_ * C_ * W_];       // per-plane col sums  [B][C][W]
__device__ float g_T [B_ * R_ * C_];       // p[r]*sigmoid(Cw)    [B][R][C]
__device__ float g_Hw[B_ * H_ * R_];       // sigmoid(Hw)         [B][H][R]
__device__ float g_Ww[B_ * R_ * W_];       // sigmoid(Ww)         [B][R][W]

// ---------------- helpers -------------------------------------------------
__device__ __forceinline__ unsigned long long pk2(float x, float y) {
    unsigned long long r;
    asm("mov.b64 %0, {%1, %2};" : "=l"(r) : "f"(x), "f"(y));
    return r;
}
__device__ __forceinline__ void fma2(unsigned long long& d,
                                     unsigned long long a,
                                     unsigned long long b) {
    asm("fma.rn.f32x2 %0, %1, %2, %3;" : "=l"(d) : "l"(a), "l"(b), "l"(d));
}
__device__ __forceinline__ unsigned long long add2(unsigned long long a,
                                                   unsigned long long b) {
    unsigned long long r;
    asm("add.rn.f32x2 %0, %1, %2;" : "=l"(r) : "l"(a), "l"(b));
    return r;
}
__device__ __forceinline__ float2 upk2(unsigned long long v) {
    float2 f;
    asm("mov.b64 {%0, %1}, %2;" : "=f"(f.x), "=f"(f.y) : "l"(v));
    return f;
}
__device__ __forceinline__ unsigned long long shfl64(unsigned long long v, int off) {
    const unsigned lo = __shfl_xor_sync(0xffffffffu, (unsigned)(v & 0xffffffffu), off);
    const unsigned hi = __shfl_xor_sync(0xffffffffu, (unsigned)(v >> 32), off);
    return ((unsigned long long)hi << 32) | lo;
}
__device__ __forceinline__ float sigmoidf_(float x) {
    return 1.0f / (1.0f + expf(-x));
}
__device__ __forceinline__ uint32_t tf32_of(float x) {
    uint32_t t;
    asm("cvt.rna.tf32.f32 %0, %1;" : "=r"(t) : "f"(x));
    return t;
}
// mma.sync m16n8k8 tf32: D += A(16x8 row) * B(8x8 col)
__device__ __forceinline__ void mma_tf32(float (&d)[4],
        uint32_t a0, uint32_t a1, uint32_t a2, uint32_t a3,
        uint32_t b0, uint32_t b1) {
    asm("mma.sync.aligned.m16n8k8.row.col.f32.tf32.tf32.f32 "
        "{%0,%1,%2,%3}, {%4,%5,%6,%7}, {%8,%9}, {%0,%1,%2,%3};"
        : "+f"(d[0]), "+f"(d[1]), "+f"(d[2]), "+f"(d[3])
        : "r"(a0), "r"(a1), "r"(a2), "r"(a3), "r"(b0), "r"(b1));
}

// Scalar multi-value butterfly (16 batches over 32 lanes, 17 shfls).
__device__ __forceinline__ void butterfly16(float (&acc)[B_], int lane) {
    #pragma unroll
    for (int off = 16; off >= 2; off >>= 1) {
        const int nv = off >> 1;
        const bool hi = (lane & off) != 0;
        #pragma unroll
        for (int j = 0; j < nv; j++) {
            float send = hi ? acc[j] : acc[j + nv];
            float recv = __shfl_xor_sync(0xffffffffu, send, off);
            acc[j] = (hi ? acc[j + nv] : acc[j]) + recv;
        }
    }
    acc[0] += __shfl_xor_sync(0xffffffffu, acc[0], 1);
}

// Packed butterfly: 8 f32x2 values over 32 lanes.
__device__ __forceinline__ void butterfly8p(unsigned long long (&v)[8], int lane) {
    #pragma unroll
    for (int off = 16; off >= 4; off >>= 1) {
        const int nv = off >> 2;
        const bool hi = (lane & off) != 0;
        #pragma unroll
        for (int j = 0; j < nv; j++) {
            unsigned long long send = hi ? v[j] : v[j + nv];
            unsigned long long recv = shfl64(send, off);
            v[j] = add2(hi ? v[j + nv] : v[j], recv);
        }
    }
    v[0] = add2(v[0], shfl64(v[0], 2));
    v[0] = add2(v[0], shfl64(v[0], 1));
}

// ---------------- kernel 1: per-plane pools ------------------------------
__global__ void __launch_bounds__(192) pool_kernel(const float* __restrict__ X) {
    const int c = blockIdx.x;
    const int b = blockIdx.y;
    const float* plane = X + ((b * C_ + c) * H_) * (long)W_;

    const int tid  = threadIdx.x;
    const int warp = tid >> 5;
    const int lane = tid & 31;

    __shared__ float scs[6][W_];
    __shared__ float swt[6];

    float col0 = 0.f, col1 = 0.f, col2 = 0.f, col3 = 0.f, col4 = 0.f, col5 = 0.f;
    float tot = 0.f;

    const int h0 = warp * 32;
    for (int i = 0; i < 32; i++) {
        const int h = h0 + i;
        const float* row = plane + h * W_;
        float v0 = row[lane +   0];
        float v1 = row[lane +  32];
        float v2 = row[lane +  64];
        float v3 = row[lane +  96];
        float v4 = row[lane + 128];
        float v5 = row[lane + 160];
        col0 += v0; col1 += v1; col2 += v2; col3 += v3; col4 += v4; col5 += v5;
        float rs = ((v0 + v1) + (v2 + v3)) + (v4 + v5);
        #pragma unroll
        for (int off = 16; off >= 1; off >>= 1)
            rs += __shfl_down_sync(0xffffffffu, rs, off);
        if (lane == 0) {
            g_RS[(b * C_ + c) * H_ + h] = rs;
            tot += rs;
        }
    }
    scs[warp][lane +   0] = col0;
    scs[warp][lane +  32] = col1;
    scs[warp][lane +  64] = col2;
    scs[warp][lane +  96] = col3;
    scs[warp][lane + 128] = col4;
    scs[warp][lane + 160] = col5;
    if (lane == 0) swt[warp] = tot;
    __syncthreads();

    float cs = 0.f;
    #pragma unroll
    for (int j = 0; j < 6; j++) cs += scs[j][tid];
    g_CS[(b * C_ + c) * W_ + tid] = cs;

    if (tid == 0) {
        float t = 0.f;
        #pragma unroll
        for (int j = 0; j < 6; j++) t += swt[j];
        g_cp[b * C_ + c] = t * (1.0f / (H_ * (float)W_));
    }
}

// ---------------- kernel 2: reduce RS/CS over c -> hp, wp ----------------
__global__ void hw_pool_kernel() {
    const int i = blockIdx.x * blockDim.x + threadIdx.x;  // 0 .. B*H-1
    if (i >= B_ * H_) return;
    const int b = i / H_;
    const int h = i - b * H_;
    float s1 = 0.f, s2 = 0.f;
    for (int c = 0; c < C_; c++) {
        s1 += g_RS[(b * C_ + c) * H_ + h];
        s2 += g_CS[(b * C_ + c) * W_ + h];
    }
    g_hp[i] = s1 * (1.0f / (C_ * (float)W_));
    g_wp[i] = s2 * (1.0f / (C_ * (float)H_));
}

// ---------------- kernel 3: ALL sigmoid weights ---------------------------
__global__ void __launch_bounds__(256) weights_kernel(
        const float* __restrict__ Wh, const float* __restrict__ bh,
        const float* __restrict__ Wwp, const float* __restrict__ bw,
        const float* __restrict__ Wc, const float* __restrict__ bc,
        const float* __restrict__ p) {
    const int tid  = threadIdx.x;
    const int warp = tid >> 5;
    const int lane = tid & 31;
    const int branch = blockIdx.y;

    __shared__ unsigned long long sp2[8][H_];   // packed pools (b, b+8)
    __shared__ float spc[B_][C_];               // C-branch pools

    if (branch == 2) {
        if (blockIdx.x >= (R_ * C_) / 16) return;
        for (int i = tid; i < B_ * C_; i += 256)
            spc[i >> 6][i & 63] = g_cp[i];
        __syncthreads();

        const int m0 = blockIdx.x * 16 + warp * 2;   // 0..4094
        const int m1 = m0 + 1;
        const float* w0 = Wc + m0 * C_;
        const float* w1 = Wc + m1 * C_;
        const float a0 = w0[lane], a1 = w0[lane + 32];
        const float b0 = w1[lane], b1 = w1[lane + 32];

        float acc0[B_], acc1[B_];
        #pragma unroll
        for (int b = 0; b < B_; b++) {
            const float p0 = spc[b][lane], p1 = spc[b][lane + 32];
            acc0[b] = fmaf(a1, p1, a0 * p0);
            acc1[b] = fmaf(b1, p1, b0 * p0);
        }
        butterfly16(acc0, lane);
        butterfly16(acc1, lane);

        if ((lane & 1) == 0) {
            const int batch = lane >> 1;
            const int r0 = m0 >> 6, d0 = m0 & 63;
            const int r1 = m1 >> 6, d1 = m1 & 63;
            g_T[(batch * R_ + r0) * C_ + d0] = p[r0] * sigmoidf_(acc0[0] + bc[m0]);
            g_T[(batch * R_ + r1) * C_ + d1] = p[r1] * sigmoidf_(acc1[0] + bc[m1]);
        }
        return;
    }

    // ---- H/W branches: rows of 192, batch-packed path ----
    {
        const float* pool = branch ? g_wp : g_hp;
        for (int i = tid; i < 8 * H_; i += 256) {
            const int j = i / H_;
            const int h = i - j * H_;
            sp2[j][h] = pk2(pool[j * H_ + h], pool[(j + 8) * H_ + h]);
        }
    }
    __syncthreads();

    const int m0 = blockIdx.x * 16 + warp * 2;   // 0..12286
    const int m1 = m0 + 1;
    const float* Wsrc = branch ? Wwp : Wh;
    const float* bsrc = branch ? bw  : bh;
    const float* wrow0 = Wsrc + (long)m0 * H_;
    const float* wrow1 = Wsrc + (long)m1 * H_;

    float wa[6], wb[6];
    #pragma unroll
    for (int k = 0; k < 6; k++) wa[k] = wrow0[lane + 32 * k];
    #pragma unroll
    for (int k = 0; k < 6; k++) wb[k] = wrow1[lane + 32 * k];

    unsigned long long acc0[8], acc1[8];
    #pragma unroll
    for (int j = 0; j < 8; j++) { acc0[j] = 0ull; acc1[j] = 0ull; }

    #pragma unroll
    for (int k = 0; k < 6; k++) {
        const unsigned long long wA = pk2(wa[k], wa[k]);
        const unsigned long long wB = pk2(wb[k], wb[k]);
        const int hidx = lane + 32 * k;
        #pragma unroll
        for (int j = 0; j < 8; j++) {
            const unsigned long long pv = sp2[j][hidx];
            fma2(acc0[j], wA, pv);
            fma2(acc1[j], wB, pv);
        }
    }
    butterfly8p(acc0, lane);
    butterfly8p(acc1, lane);

    if ((lane & 3) == 0) {
        const int j  = lane >> 2;          // batch pair (j, j+8)
        const int r0 = m0 / H_, d0 = m0 - r0 * H_;
        const int r1 = m1 / H_, d1 = m1 - r1 * H_;
        const float bias0 = bsrc[m0];
        const float bias1 = bsrc[m1];
        const float2 q0 = upk2(acc0[0]);
        const float2 q1 = upk2(acc1[0]);
        const float v0a = sigmoidf_(q0.x + bias0);
        const float v0b = sigmoidf_(q0.y + bias0);
        const float v1a = sigmoidf_(q1.x + bias1);
        const float v1b = sigmoidf_(q1.y + bias1);
        if (branch == 0) {
            g_Hw[((j    ) * H_ + d0) * R_ + r0] = v0a;   // [B][H][R]
            g_Hw[((j + 8) * H_ + d0) * R_ + r0] = v0b;
            g_Hw[((j    ) * H_ + d1) * R_ + r1] = v1a;
            g_Hw[((j + 8) * H_ + d1) * R_ + r1] = v1b;
        } else {
            g_Ww[((j    ) * R_ + r0) * W_ + d0] = v0a;   // [B][R][W]
            g_Ww[((j + 8) * R_ + r0) * W_ + d0] = v0b;
            g_Ww[((j    ) * R_ + r1) * W_ + d1] = v1a;
            g_Ww[((j + 8) * R_ + r1) * W_ + d1] = v1b;
        }
    }
}

// ---------------- kernel 4: tensor-core main GEMM + elementwise ----------
// Block = (h, b), 256 threads = 8 warps. Per block: D[64c,192w] =
// Mt[64c,64r] x V[64r,192w] via mma.sync m16n8k8 tf32.
// smem (dynamic, tf32 bit patterns):
//   sMt[c][r] padded rpad=68  (A fragment loads hit 32 distinct banks)
//   sV [r][w] padded wpad=200 (B fragment loads hit 32 distinct banks)
// Warp owns a 24-w strip x all 64 c: per k-step 16+6 LDS.32 feed 12 MMAs.
// Epilogue multiplies by X with float2 (32B-sector aligned) accesses.
#define RPAD 68
#define WPAD 200
#define SMT_U32 (C_ * RPAD)            // 4352
#define SV_U32  (R_ * WPAD)            // 12800
#define MAIN_SMEM_BYTES ((SMT_U32 + SV_U32 + R_) * 4)

extern __shared__ uint32_t smem_u32[];
__global__ void __launch_bounds__(256, 2) main_tc_kernel(const float* __restrict__ X,
                                                         float* __restrict__ out) {
    const int h = blockIdx.x;   // 0..191
    const int b = blockIdx.y;   // 0..15

    uint32_t* sMt = smem_u32;             // [c][r] tf32
    uint32_t* sV  = smem_u32 + SMT_U32;   // [r][w] tf32
    float*    sh  = (float*)(smem_u32 + SMT_U32 + SV_U32);

    const int tid  = threadIdx.x;
    const int warp = tid >> 5;
    const int lane = tid & 31;
    const int g    = lane >> 2;   // fragment group row
    const int t    = lane & 3;    // thread in group

    if (tid < R_) sh[tid] = g_Hw[(b * H_ + h) * R_ + tid];
    __syncthreads();

    // fill sMt[c][r] = tf32( T[b][r][c] * sh[r] )   (transposed store)
    {
        const float* Tb = g_T + b * (R_ * C_);
        for (int i = tid; i < R_ * C_; i += 256) {
            const int r = i >> 6;
            const int c = i & 63;
            sMt[c * RPAD + r] = tf32_of(Tb[i] * sh[r]);
        }
    }
    // fill sV[r][w] = tf32( Ww[b][r][w] )
    {
        const float4* Wb4 = (const float4*)(g_Ww + b * (R_ * W_));
        for (int i = tid; i < (R_ * W_) / 4; i += 256) {
            const float4 v = Wb4[i];
            const int r = i / (W_ / 4);
            const int w4 = i - r * (W_ / 4);
            uint32_t* dst = sV + r * WPAD + w4 * 4;
            dst[0] = tf32_of(v.x);
            dst[1] = tf32_of(v.y);
            dst[2] = tf32_of(v.z);
            dst[3] = tf32_of(v.w);
        }
    }
    __syncthreads();

    const int n0 = warp * 24;     // w strip

    float d[4][3][4];             // [m-tile][n-tile][frag]
    #pragma unroll
    for (int mi = 0; mi < 4; mi++)
        #pragma unroll
        for (int ni = 0; ni < 3; ni++)
            #pragma unroll
            for (int q = 0; q < 4; q++) d[mi][ni][q] = 0.f;

    #pragma unroll
    for (int k0 = 0; k0 < R_; k0 += 8) {
        uint32_t a[4][4];
        #pragma unroll
        for (int mi = 0; mi < 4; mi++) {
            const int row0 = (16 * mi + g) * RPAD + k0 + t;
            a[mi][0] = sMt[row0];
            a[mi][1] = sMt[row0 + 8 * RPAD];
            a[mi][2] = sMt[row0 + 4];
            a[mi][3] = sMt[row0 + 8 * RPAD + 4];
        }
        uint32_t bb[3][2];
        #pragma unroll
        for (int ni = 0; ni < 3; ni++) {
            const int base = (k0 + t) * WPAD + n0 + 8 * ni + g;
            bb[ni][0] = sV[base];
            bb[ni][1] = sV[base + 4 * WPAD];
        }
        #pragma unroll
        for (int mi = 0; mi < 4; mi++)
            #pragma unroll
            for (int ni = 0; ni < 3; ni++)
                mma_tf32(d[mi][ni], a[mi][0], a[mi][1], a[mi][2], a[mi][3],
                         bb[ni][0], bb[ni][1]);
    }

    // epilogue: D frag element map -> c rows {16mi+g, +8}, w cols {n0+8ni+2t, +1}
    #pragma unroll
    for (int mi = 0; mi < 4; mi++) {
        #pragma unroll
        for (int ni = 0; ni < 3; ni++) {
            const int c0 = 16 * mi + g;
            const int w  = n0 + 8 * ni + 2 * t;
            const long i0 = ((long)(b * C_ + c0) * H_ + h) * W_ + w;
            const long i1 = i0 + 8L * H_ * W_;

            const float2 x0 = *(const float2*)(X + i0);
            float2 o0;
            o0.x = d[mi][ni][0] * x0.x;
            o0.y = d[mi][ni][1] * x0.y;
            *(float2*)(out + i0) = o0;

            const float2 x1 = *(const float2*)(X + i1);
            float2 o1;
            o1.x = d[mi][ni][2] * x1.x;
            o1.y = d[mi][ni][3] * x1.y;
            *(float2*)(out + i1) = o1;
        }
    }
}

// ---------------- launch ---------------------------------------------------
extern "C" void kernel_launch(void* const* d_in, const int* in_sizes, int n_in,
                              void* d_out, int out_size) {
    const float* X   = (const float*)d_in[0];
    const float* p   = (const float*)d_in[1];
    const float* Wc  = (const float*)d_in[2];
    const float* bc  = (const float*)d_in[3];
    const float* Wh  = (const float*)d_in[4];
    const float* bh  = (const float*)d_in[5];
    const float* Wwp = (const float*)d_in[6];
    const float* bw  = (const float*)d_in[7];
    float* out = (float*)d_out;

    static int attr_done = 0;
    if (!attr_done) {
        cudaFuncSetAttribute(main_tc_kernel,
                             cudaFuncAttributeMaxDynamicSharedMemorySize,
                             MAIN_SMEM_BYTES);
        attr_done = 1;
    }

    pool_kernel<<<dim3(C_, B_), 192>>>(X);                               // 1
    hw_pool_kernel<<<(B_ * H_ + 255) / 256, 256>>>();                    // 2
    weights_kernel<<<dim3((R_ * H_) / 16, 3), 256>>>(Wh, bh, Wwp, bw,    // 3
                                                     Wc, bc, p);
    main_tc_kernel<<<dim3(H_, B_), 256, MAIN_SMEM_BYTES>>>(X, out);      // 4
}

// round 15
// speedup vs baseline: 1.1953x; 1.1953x over previous
#include <cuda_runtime.h>
#include <math.h>
#include <stdint.h>

#define B_ 16
#define C_ 64
#define H_ 192
#define W_ 192
#define R_ 64

// ---------------- scratch (device globals; no allocation) ----------------
__device__ float g_cp[B_ * C_];            // [B][C]
__device__ float g_hp[B_ * H_];            // [B][H]
__device__ float g_wp[B_ * W_];            // [B][W]
__device__ float g_RS[B_ * C_ * H_];       // per-plane row sums  [B][C][H]
__device__ float g_CS[B_ * C_ * W_];       // per-plane col sums  [B][C][W]
__device__ float g_T [B_ * R_ * C_];       // p[r]*sigmoid(Cw)    [B][R][C]
__device__ float g_Hw[B_ * H_ * R_];       // sigmoid(Hw)         [B][H][R]
__device__ float g_Ww[B_ * R_ * W_];       // sigmoid(Ww)         [B][R][W]

// ---------------- helpers -------------------------------------------------
__device__ __forceinline__ unsigned long long pk2(float x, float y) {
    unsigned long long r;
    asm("mov.b64 %0, {%1, %2};" : "=l"(r) : "f"(x), "f"(y));
    return r;
}
__device__ __forceinline__ void fma2(unsigned long long& d,
                                     unsigned long long a,
                                     unsigned long long b) {
    asm("fma.rn.f32x2 %0, %1, %2, %3;" : "=l"(d) : "l"(a), "l"(b), "l"(d));
}
__device__ __forceinline__ unsigned long long add2(unsigned long long a,
                                                   unsigned long long b) {
    unsigned long long r;
    asm("add.rn.f32x2 %0, %1, %2;" : "=l"(r) : "l"(a), "l"(b));
    return r;
}
__device__ __forceinline__ float2 upk2(unsigned long long v) {
    float2 f;
    asm("mov.b64 {%0, %1}, %2;" : "=f"(f.x), "=f"(f.y) : "l"(v));
    return f;
}
__device__ __forceinline__ unsigned long long shfl64(unsigned long long v, int off) {
    const unsigned lo = __shfl_xor_sync(0xffffffffu, (unsigned)(v & 0xffffffffu), off);
    const unsigned hi = __shfl_xor_sync(0xffffffffu, (unsigned)(v >> 32), off);
    return ((unsigned long long)hi << 32) | lo;
}
__device__ __forceinline__ float sigmoidf_(float x) {
    return 1.0f / (1.0f + expf(-x));
}
__device__ __forceinline__ uint32_t tf32_of(float x) {
    uint32_t t;
    asm("cvt.rna.tf32.f32 %0, %1;" : "=r"(t) : "f"(x));
    return t;
}
// mma.sync m16n8k8 tf32: D += A(16x8 row) * B(8x8 col)
__device__ __forceinline__ void mma_tf32(float (&d)[4],
        uint32_t a0, uint32_t a1, uint32_t a2, uint32_t a3,
        uint32_t b0, uint32_t b1) {
    asm("mma.sync.aligned.m16n8k8.row.col.f32.tf32.tf32.f32 "
        "{%0,%1,%2,%3}, {%4,%5,%6,%7}, {%8,%9}, {%0,%1,%2,%3};"
        : "+f"(d[0]), "+f"(d[1]), "+f"(d[2]), "+f"(d[3])
        : "r"(a0), "r"(a1), "r"(a2), "r"(a3), "r"(b0), "r"(b1));
}

// Scalar multi-value butterfly (16 batches over 32 lanes, 17 shfls).
__device__ __forceinline__ void butterfly16(float (&acc)[B_], int lane) {
    #pragma unroll
    for (int off = 16; off >= 2; off >>= 1) {
        const int nv = off >> 1;
        const bool hi = (lane & off) != 0;
        #pragma unroll
        for (int j = 0; j < nv; j++) {
            float send = hi ? acc[j] : acc[j + nv];
            float recv = __shfl_xor_sync(0xffffffffu, send, off);
            acc[j] = (hi ? acc[j + nv] : acc[j]) + recv;
        }
    }
    acc[0] += __shfl_xor_sync(0xffffffffu, acc[0], 1);
}

// Packed butterfly: 8 f32x2 values over 32 lanes.
__device__ __forceinline__ void butterfly8p(unsigned long long (&v)[8], int lane) {
    #pragma unroll
    for (int off = 16; off >= 4; off >>= 1) {
        const int nv = off >> 2;
        const bool hi = (lane & off) != 0;
        #pragma unroll
        for (int j = 0; j < nv; j++) {
            unsigned long long send = hi ? v[j] : v[j + nv];
            unsigned long long recv = shfl64(send, off);
            v[j] = add2(hi ? v[j + nv] : v[j], recv);
        }
    }
    v[0] = add2(v[0], shfl64(v[0], 2));
    v[0] = add2(v[0], shfl64(v[0], 1));
}

// ---------------- kernel 1: per-plane pools ------------------------------
__global__ void __launch_bounds__(192) pool_kernel(const float* __restrict__ X) {
    const int c = blockIdx.x;
    const int b = blockIdx.y;
    const float* plane = X + ((b * C_ + c) * H_) * (long)W_;

    const int tid  = threadIdx.x;
    const int warp = tid >> 5;
    const int lane = tid & 31;

    __shared__ float scs[6][W_];
    __shared__ float swt[6];

    float col0 = 0.f, col1 = 0.f, col2 = 0.f, col3 = 0.f, col4 = 0.f, col5 = 0.f;
    float tot = 0.f;

    const int h0 = warp * 32;
    for (int i = 0; i < 32; i++) {
        const int h = h0 + i;
        const float* row = plane + h * W_;
        float v0 = row[lane +   0];
        float v1 = row[lane +  32];
        float v2 = row[lane +  64];
        float v3 = row[lane +  96];
        float v4 = row[lane + 128];
        float v5 = row[lane + 160];
        col0 += v0; col1 += v1; col2 += v2; col3 += v3; col4 += v4; col5 += v5;
        float rs = ((v0 + v1) + (v2 + v3)) + (v4 + v5);
        #pragma unroll
        for (int off = 16; off >= 1; off >>= 1)
            rs += __shfl_down_sync(0xffffffffu, rs, off);
        if (lane == 0) {
            g_RS[(b * C_ + c) * H_ + h] = rs;
            tot += rs;
        }
    }
    scs[warp][lane +   0] = col0;
    scs[warp][lane +  32] = col1;
    scs[warp][lane +  64] = col2;
    scs[warp][lane +  96] = col3;
    scs[warp][lane + 128] = col4;
    scs[warp][lane + 160] = col5;
    if (lane == 0) swt[warp] = tot;
    __syncthreads();

    float cs = 0.f;
    #pragma unroll
    for (int j = 0; j < 6; j++) cs += scs[j][tid];
    g_CS[(b * C_ + c) * W_ + tid] = cs;

    if (tid == 0) {
        float t = 0.f;
        #pragma unroll
        for (int j = 0; j < 6; j++) t += swt[j];
        g_cp[b * C_ + c] = t * (1.0f / (H_ * (float)W_));
    }
}

// ---------------- kernel 2: reduce RS/CS over c -> hp, wp ----------------
__global__ void hw_pool_kernel() {
    const int i = blockIdx.x * blockDim.x + threadIdx.x;  // 0 .. B*H-1
    if (i >= B_ * H_) return;
    const int b = i / H_;
    const int h = i - b * H_;
    float s1 = 0.f, s2 = 0.f;
    for (int c = 0; c < C_; c++) {
        s1 += g_RS[(b * C_ + c) * H_ + h];
        s2 += g_CS[(b * C_ + c) * W_ + h];
    }
    g_hp[i] = s1 * (1.0f / (C_ * (float)W_));
    g_wp[i] = s2 * (1.0f / (C_ * (float)H_));
}

// ---------------- kernel 3: ALL sigmoid weights ---------------------------
__global__ void __launch_bounds__(256) weights_kernel(
        const float* __restrict__ Wh, const float* __restrict__ bh,
        const float* __restrict__ Wwp, const float* __restrict__ bw,
        const float* __restrict__ Wc, const float* __restrict__ bc,
        const float* __restrict__ p) {
    const int tid  = threadIdx.x;
    const int warp = tid >> 5;
    const int lane = tid & 31;
    const int branch = blockIdx.y;

    __shared__ unsigned long long sp2[8][H_];   // packed pools (b, b+8)
    __shared__ float spc[B_][C_];               // C-branch pools

    if (branch == 2) {
        if (blockIdx.x >= (R_ * C_) / 16) return;
        for (int i = tid; i < B_ * C_; i += 256)
            spc[i >> 6][i & 63] = g_cp[i];
        __syncthreads();

        const int m0 = blockIdx.x * 16 + warp * 2;   // 0..4094
        const int m1 = m0 + 1;
        const float* w0 = Wc + m0 * C_;
        const float* w1 = Wc + m1 * C_;
        const float a0 = w0[lane], a1 = w0[lane + 32];
        const float b0 = w1[lane], b1 = w1[lane + 32];

        float acc0[B_], acc1[B_];
        #pragma unroll
        for (int b = 0; b < B_; b++) {
            const float p0 = spc[b][lane], p1 = spc[b][lane + 32];
            acc0[b] = fmaf(a1, p1, a0 * p0);
            acc1[b] = fmaf(b1, p1, b0 * p0);
        }
        butterfly16(acc0, lane);
        butterfly16(acc1, lane);

        if ((lane & 1) == 0) {
            const int batch = lane >> 1;
            const int r0 = m0 >> 6, d0 = m0 & 63;
            const int r1 = m1 >> 6, d1 = m1 & 63;
            g_T[(batch * R_ + r0) * C_ + d0] = p[r0] * sigmoidf_(acc0[0] + bc[m0]);
            g_T[(batch * R_ + r1) * C_ + d1] = p[r1] * sigmoidf_(acc1[0] + bc[m1]);
        }
        return;
    }

    // ---- H/W branches: rows of 192, batch-packed path ----
    {
        const float* pool = branch ? g_wp : g_hp;
        for (int i = tid; i < 8 * H_; i += 256) {
            const int j = i / H_;
            const int h = i - j * H_;
            sp2[j][h] = pk2(pool[j * H_ + h], pool[(j + 8) * H_ + h]);
        }
    }
    __syncthreads();

    const int m0 = blockIdx.x * 16 + warp * 2;   // 0..12286
    const int m1 = m0 + 1;
    const float* Wsrc = branch ? Wwp : Wh;
    const float* bsrc = branch ? bw  : bh;
    const float* wrow0 = Wsrc + (long)m0 * H_;
    const float* wrow1 = Wsrc + (long)m1 * H_;

    float wa[6], wb[6];
    #pragma unroll
    for (int k = 0; k < 6; k++) wa[k] = wrow0[lane + 32 * k];
    #pragma unroll
    for (int k = 0; k < 6; k++) wb[k] = wrow1[lane + 32 * k];

    unsigned long long acc0[8], acc1[8];
    #pragma unroll
    for (int j = 0; j < 8; j++) { acc0[j] = 0ull; acc1[j] = 0ull; }

    #pragma unroll
    for (int k = 0; k < 6; k++) {
        const unsigned long long wA = pk2(wa[k], wa[k]);
        const unsigned long long wB = pk2(wb[k], wb[k]);
        const int hidx = lane + 32 * k;
        #pragma unroll
        for (int j = 0; j < 8; j++) {
            const unsigned long long pv = sp2[j][hidx];
            fma2(acc0[j], wA, pv);
            fma2(acc1[j], wB, pv);
        }
    }
    butterfly8p(acc0, lane);
    butterfly8p(acc1, lane);

    if ((lane & 3) == 0) {
        const int j  = lane >> 2;          // batch pair (j, j+8)
        const int r0 = m0 / H_, d0 = m0 - r0 * H_;
        const int r1 = m1 / H_, d1 = m1 - r1 * H_;
        const float bias0 = bsrc[m0];
        const float bias1 = bsrc[m1];
        const float2 q0 = upk2(acc0[0]);
        const float2 q1 = upk2(acc1[0]);
        const float v0a = sigmoidf_(q0.x + bias0);
        const float v0b = sigmoidf_(q0.y + bias0);
        const float v1a = sigmoidf_(q1.x + bias1);
        const float v1b = sigmoidf_(q1.y + bias1);
        if (branch == 0) {
            g_Hw[((j    ) * H_ + d0) * R_ + r0] = v0a;   // [B][H][R]
            g_Hw[((j + 8) * H_ + d0) * R_ + r0] = v0b;
            g_Hw[((j    ) * H_ + d1) * R_ + r1] = v1a;
            g_Hw[((j + 8) * H_ + d1) * R_ + r1] = v1b;
        } else {
            g_Ww[((j    ) * R_ + r0) * W_ + d0] = v0a;   // [B][R][W]
            g_Ww[((j + 8) * R_ + r0) * W_ + d0] = v0b;
            g_Ww[((j    ) * R_ + r1) * W_ + d1] = v1a;
            g_Ww[((j + 8) * R_ + r1) * W_ + d1] = v1b;
        }
    }
}

// ---------------- kernel 4: tensor-core main GEMM + elementwise ----------
// Block = (h, b), 512 threads = 16 warps. D[64c,192w] = Mt[64c,64r] x
// V[64r,192w] via mma.sync m16n8k8 tf32.
// Warp (warp_m = warp&1, warp_n = warp>>3... see below) owns 32c x 24w:
// d[2][3][4] = 24 accum regs -> ~60 regs/thread, 512thr x 2 blocks/SM =
// 32 warps/SM (2.1x R14's occupancy; kernel was pure latency-bound).
#define RPAD 68
#define WPAD 200
#define SMT_U32 (C_ * RPAD)            // 4352
#define SV_U32  (R_ * WPAD)            // 12800
#define MAIN_SMEM_BYTES ((SMT_U32 + SV_U32 + R_) * 4)

extern __shared__ uint32_t smem_u32[];
__global__ void __launch_bounds__(512, 2) main_tc_kernel(const float* __restrict__ X,
                                                         float* __restrict__ out) {
    const int h = blockIdx.x;   // 0..191
    const int b = blockIdx.y;   // 0..15

    uint32_t* sMt = smem_u32;             // [c][r] tf32
    uint32_t* sV  = smem_u32 + SMT_U32;   // [r][w] tf32
    float*    sh  = (float*)(smem_u32 + SMT_U32 + SV_U32);

    const int tid  = threadIdx.x;
    const int warp = tid >> 5;            // 0..15
    const int lane = tid & 31;
    const int g    = lane >> 2;           // fragment group row
    const int t    = lane & 3;            // thread in group
    const int warp_m = warp & 1;          // c half: m-tiles {2wm, 2wm+1}
    const int warp_n = warp >> 1;         // 0..7 -> 24-w strip

    if (tid < R_) sh[tid] = g_Hw[(b * H_ + h) * R_ + tid];
    __syncthreads();

    // fill sMt[c][r] = tf32( T[b][r][c] * sh[r] )   (transposed store)
    {
        const float* Tb = g_T + b * (R_ * C_);
        for (int i = tid; i < R_ * C_; i += 512) {
            const int r = i >> 6;
            const int c = i & 63;
            sMt[c * RPAD + r] = tf32_of(Tb[i] * sh[r]);
        }
    }
    // fill sV[r][w] = tf32( Ww[b][r][w] )
    {
        const float4* Wb4 = (const float4*)(g_Ww + b * (R_ * W_));
        for (int i = tid; i < (R_ * W_) / 4; i += 512) {
            const float4 v = Wb4[i];
            const int r = i / (W_ / 4);
            const int w4 = i - r * (W_ / 4);
            uint32_t* dst = sV + r * WPAD + w4 * 4;
            dst[0] = tf32_of(v.x);
            dst[1] = tf32_of(v.y);
            dst[2] = tf32_of(v.z);
            dst[3] = tf32_of(v.w);
        }
    }
    __syncthreads();

    const int n0 = warp_n * 24;   // w strip
    const int mt0 = 2 * warp_m;   // first m-tile

    float d[2][3][4];             // [m-tile][n-tile][frag]
    #pragma unroll
    for (int mi = 0; mi < 2; mi++)
        #pragma unroll
        for (int ni = 0; ni < 3; ni++)
            #pragma unroll
            for (int q = 0; q < 4; q++) d[mi][ni][q] = 0.f;

    #pragma unroll
    for (int k0 = 0; k0 < R_; k0 += 8) {
        uint32_t a[2][4];
        #pragma unroll
        for (int mi = 0; mi < 2; mi++) {
            const int row0 = (16 * (mt0 + mi) + g) * RPAD + k0 + t;
            a[mi][0] = sMt[row0];
            a[mi][1] = sMt[row0 + 8 * RPAD];
            a[mi][2] = sMt[row0 + 4];
            a[mi][3] = sMt[row0 + 8 * RPAD + 4];
        }
        uint32_t bb[3][2];
        #pragma unroll
        for (int ni = 0; ni < 3; ni++) {
            const int base = (k0 + t) * WPAD + n0 + 8 * ni + g;
            bb[ni][0] = sV[base];
            bb[ni][1] = sV[base + 4 * WPAD];
        }
        #pragma unroll
        for (int mi = 0; mi < 2; mi++)
            #pragma unroll
            for (int ni = 0; ni < 3; ni++)
                mma_tf32(d[mi][ni], a[mi][0], a[mi][1], a[mi][2], a[mi][3],
                         bb[ni][0], bb[ni][1]);
    }

    // epilogue: c rows {16(mt0+mi)+g, +8}, w cols {n0+8ni+2t, +1}
    #pragma unroll
    for (int mi = 0; mi < 2; mi++) {
        #pragma unroll
        for (int ni = 0; ni < 3; ni++) {
            const int c0 = 16 * (mt0 + mi) + g;
            const int w  = n0 + 8 * ni + 2 * t;
            const long i0 = ((long)(b * C_ + c0) * H_ + h) * W_ + w;
            const long i1 = i0 + 8L * H_ * W_;

            const float2 x0 = *(const float2*)(X + i0);
            const float2 x1 = *(const float2*)(X + i1);
            float2 o0, o1;
            o0.x = d[mi][ni][0] * x0.x;
            o0.y = d[mi][ni][1] * x0.y;
            o1.x = d[mi][ni][2] * x1.x;
            o1.y = d[mi][ni][3] * x1.y;
            *(float2*)(out + i0) = o0;
            *(float2*)(out + i1) = o1;
        }
    }
}

// ---------------- launch ---------------------------------------------------
extern "C" void kernel_launch(void* const* d_in, const int* in_sizes, int n_in,
                              void* d_out, int out_size) {
    const float* X   = (const float*)d_in[0];
    const float* p   = (const float*)d_in[1];
    const float* Wc  = (const float*)d_in[2];
    const float* bc  = (const float*)d_in[3];
    const float* Wh  = (const float*)d_in[4];
    const float* bh  = (const float*)d_in[5];
    const float* Wwp = (const float*)d_in[6];
    const float* bw  = (const float*)d_in[7];
    float* out = (float*)d_out;

    static int attr_done = 0;
    if (!attr_done) {
        cudaFuncSetAttribute(main_tc_kernel,
                             cudaFuncAttributeMaxDynamicSharedMemorySize,
                             MAIN_SMEM_BYTES);
        attr_done = 1;
    }

    pool_kernel<<<dim3(C_, B_), 192>>>(X);                               // 1
    hw_pool_kernel<<<(B_ * H_ + 255) / 256, 256>>>();                    // 2
    weights_kernel<<<dim3((R_ * H_) / 16, 3), 256>>>(Wh, bh, Wwp, bw,    // 3
                                                     Wc, bc, p);
    main_tc_kernel<<<dim3(H_, B_), 512, MAIN_SMEM_BYTES>>>(X, out);      // 4
}

// round 17
// speedup vs baseline: 1.2192x; 1.0200x over previous
#include <cuda_runtime.h>
#include <math.h>
#include <stdint.h>

#define B_ 16
#define C_ 64
#define H_ 192
#define W_ 192
#define R_ 64

// ---------------- scratch (device globals; no allocation) ----------------
__device__ float g_cp[B_ * C_];            // [B][C]
__device__ float g_hp[B_ * H_];            // [B][H]
__device__ float g_wp[B_ * W_];            // [B][W]
__device__ float g_RS[B_ * C_ * H_];       // per-plane row sums  [B][C][H]
__device__ float g_CS[B_ * C_ * W_];       // per-plane col sums  [B][C][W]
__device__ float g_T [B_ * R_ * C_];       // tf32(p[r]*sigmoid)  [B][R][C]
__device__ float g_Hw[B_ * H_ * R_];       // sigmoid (fp32)      [B][H][R]
__device__ float g_Ww[B_ * R_ * W_];       // tf32(sigmoid)       [B][R][W]

// ---------------- helpers -------------------------------------------------
__device__ __forceinline__ unsigned long long pk2(float x, float y) {
    unsigned long long r;
    asm("mov.b64 %0, {%1, %2};" : "=l"(r) : "f"(x), "f"(y));
    return r;
}
__device__ __forceinline__ void fma2(unsigned long long& d,
                                     unsigned long long a,
                                     unsigned long long b) {
    asm("fma.rn.f32x2 %0, %1, %2, %3;" : "=l"(d) : "l"(a), "l"(b), "l"(d));
}
__device__ __forceinline__ unsigned long long add2(unsigned long long a,
                                                   unsigned long long b) {
    unsigned long long r;
    asm("add.rn.f32x2 %0, %1, %2;" : "=l"(r) : "l"(a), "l"(b));
    return r;
}
__device__ __forceinline__ float2 upk2(unsigned long long v) {
    float2 f;
    asm("mov.b64 {%0, %1}, %2;" : "=f"(f.x), "=f"(f.y) : "l"(v));
    return f;
}
__device__ __forceinline__ unsigned long long shfl64(unsigned long long v, int off) {
    const unsigned lo = __shfl_xor_sync(0xffffffffu, (unsigned)(v & 0xffffffffu), off);
    const unsigned hi = __shfl_xor_sync(0xffffffffu, (unsigned)(v >> 32), off);
    return ((unsigned long long)hi << 32) | lo;
}
__device__ __forceinline__ float sigmoidf_(float x) {
    return 1.0f / (1.0f + expf(-x));
}
__device__ __forceinline__ uint32_t tf32_of(float x) {
    uint32_t t;
    asm("cvt.rna.tf32.f32 %0, %1;" : "=r"(t) : "f"(x));
    return t;
}
__device__ __forceinline__ float tf32f(float x) {
    return __uint_as_float(tf32_of(x));
}
// mma.sync m16n8k8 tf32: D += A(16x8 row) * B(8x8 col)
__device__ __forceinline__ void mma_tf32(float (&d)[4],
        uint32_t a0, uint32_t a1, uint32_t a2, uint32_t a3,
        uint32_t b0, uint32_t b1) {
    asm("mma.sync.aligned.m16n8k8.row.col.f32.tf32.tf32.f32 "
        "{%0,%1,%2,%3}, {%4,%5,%6,%7}, {%8,%9}, {%0,%1,%2,%3};"
        : "+f"(d[0]), "+f"(d[1]), "+f"(d[2]), "+f"(d[3])
        : "r"(a0), "r"(a1), "r"(a2), "r"(a3), "r"(b0), "r"(b1));
}

// Scalar multi-value butterfly (16 batches over 32 lanes, 17 shfls).
__device__ __forceinline__ void butterfly16(float (&acc)[B_], int lane) {
    #pragma unroll
    for (int off = 16; off >= 2; off >>= 1) {
        const int nv = off >> 1;
        const bool hi = (lane & off) != 0;
        #pragma unroll
        for (int j = 0; j < nv; j++) {
            float send = hi ? acc[j] : acc[j + nv];
            float recv = __shfl_xor_sync(0xffffffffu, send, off);
            acc[j] = (hi ? acc[j + nv] : acc[j]) + recv;
        }
    }
    acc[0] += __shfl_xor_sync(0xffffffffu, acc[0], 1);
}

// Packed butterfly: 8 f32x2 values over 32 lanes.
__device__ __forceinline__ void butterfly8p(unsigned long long (&v)[8], int lane) {
    #pragma unroll
    for (int off = 16; off >= 4; off >>= 1) {
        const int nv = off >> 2;
        const bool hi = (lane & off) != 0;
        #pragma unroll
        for (int j = 0; j < nv; j++) {
            unsigned long long send = hi ? v[j] : v[j + nv];
            unsigned long long recv = shfl64(send, off);
            v[j] = add2(hi ? v[j + nv] : v[j], recv);
        }
    }
    v[0] = add2(v[0], shfl64(v[0], 2));
    v[0] = add2(v[0], shfl64(v[0], 1));
}

// ---------------- kernel 1: per-plane pools ------------------------------
__global__ void __launch_bounds__(192) pool_kernel(const float* __restrict__ X) {
    const int c = blockIdx.x;
    const int b = blockIdx.y;
    const float* plane = X + ((b * C_ + c) * H_) * (long)W_;

    const int tid  = threadIdx.x;
    const int warp = tid >> 5;
    const int lane = tid & 31;

    __shared__ float scs[6][W_];
    __shared__ float swt[6];

    float col0 = 0.f, col1 = 0.f, col2 = 0.f, col3 = 0.f, col4 = 0.f, col5 = 0.f;
    float tot = 0.f;

    const int h0 = warp * 32;
    for (int i = 0; i < 32; i++) {
        const int h = h0 + i;
        const float* row = plane + h * W_;
        float v0 = row[lane +   0];
        float v1 = row[lane +  32];
        float v2 = row[lane +  64];
        float v3 = row[lane +  96];
        float v4 = row[lane + 128];
        float v5 = row[lane + 160];
        col0 += v0; col1 += v1; col2 += v2; col3 += v3; col4 += v4; col5 += v5;
        float rs = ((v0 + v1) + (v2 + v3)) + (v4 + v5);
        #pragma unroll
        for (int off = 16; off >= 1; off >>= 1)
            rs += __shfl_down_sync(0xffffffffu, rs, off);
        if (lane == 0) {
            g_RS[(b * C_ + c) * H_ + h] = rs;
            tot += rs;
        }
    }
    scs[warp][lane +   0] = col0;
    scs[warp][lane +  32] = col1;
    scs[warp][lane +  64] = col2;
    scs[warp][lane +  96] = col3;
    scs[warp][lane + 128] = col4;
    scs[warp][lane + 160] = col5;
    if (lane == 0) swt[warp] = tot;
    __syncthreads();

    float cs = 0.f;
    #pragma unroll
    for (int j = 0; j < 6; j++) cs += scs[j][tid];
    g_CS[(b * C_ + c) * W_ + tid] = cs;

    if (tid == 0) {
        float t = 0.f;
        #pragma unroll
        for (int j = 0; j < 6; j++) t += swt[j];
        g_cp[b * C_ + c] = t * (1.0f / (H_ * (float)W_));
    }
}

// ---------------- kernel 2: reduce RS/CS over c -> hp, wp ----------------
__global__ void hw_pool_kernel() {
    const int i = blockIdx.x * blockDim.x + threadIdx.x;  // 0 .. B*H-1
    if (i >= B_ * H_) return;
    const int b = i / H_;
    const int h = i - b * H_;
    float s1 = 0.f, s2 = 0.f;
    for (int c = 0; c < C_; c++) {
        s1 += g_RS[(b * C_ + c) * H_ + h];
        s2 += g_CS[(b * C_ + c) * W_ + h];
    }
    g_hp[i] = s1 * (1.0f / (C_ * (float)W_));
    g_wp[i] = s2 * (1.0f / (C_ * (float)H_));
}

// ---------------- kernel 3: ALL sigmoid weights ---------------------------
// g_T and g_Ww are stored pre-rounded to tf32 (consumed only by main_tc).
__global__ void __launch_bounds__(256) weights_kernel(
        const float* __restrict__ Wh, const float* __restrict__ bh,
        const float* __restrict__ Wwp, const float* __restrict__ bw,
        const float* __restrict__ Wc, const float* __restrict__ bc,
        const float* __restrict__ p) {
    const int tid  = threadIdx.x;
    const int warp = tid >> 5;
    const int lane = tid & 31;
    const int branch = blockIdx.y;

    __shared__ unsigned long long sp2[8][H_];   // packed pools (b, b+8)
    __shared__ float spc[B_][C_];               // C-branch pools

    if (branch == 2) {
        if (blockIdx.x >= (R_ * C_) / 16) return;
        for (int i = tid; i < B_ * C_; i += 256)
            spc[i >> 6][i & 63] = g_cp[i];
        __syncthreads();

        const int m0 = blockIdx.x * 16 + warp * 2;   // 0..4094
        const int m1 = m0 + 1;
        const float* w0 = Wc + m0 * C_;
        const float* w1 = Wc + m1 * C_;
        const float a0 = w0[lane], a1 = w0[lane + 32];
        const float b0 = w1[lane], b1 = w1[lane + 32];

        float acc0[B_], acc1[B_];
        #pragma unroll
        for (int b = 0; b < B_; b++) {
            const float p0 = spc[b][lane], p1 = spc[b][lane + 32];
            acc0[b] = fmaf(a1, p1, a0 * p0);
            acc1[b] = fmaf(b1, p1, b0 * p0);
        }
        butterfly16(acc0, lane);
        butterfly16(acc1, lane);

        if ((lane & 1) == 0) {
            const int batch = lane >> 1;
            const int r0 = m0 >> 6, d0 = m0 & 63;
            const int r1 = m1 >> 6, d1 = m1 & 63;
            g_T[(batch * R_ + r0) * C_ + d0] = tf32f(p[r0] * sigmoidf_(acc0[0] + bc[m0]));
            g_T[(batch * R_ + r1) * C_ + d1] = tf32f(p[r1] * sigmoidf_(acc1[0] + bc[m1]));
        }
        return;
    }

    // ---- H/W branches: rows of 192, batch-packed path ----
    {
        const float* pool = branch ? g_wp : g_hp;
        for (int i = tid; i < 8 * H_; i += 256) {
            const int j = i / H_;
            const int h = i - j * H_;
            sp2[j][h] = pk2(pool[j * H_ + h], pool[(j + 8) * H_ + h]);
        }
    }
    __syncthreads();

    const int m0 = blockIdx.x * 16 + warp * 2;   // 0..12286
    const int m1 = m0 + 1;
    const float* Wsrc = branch ? Wwp : Wh;
    const float* bsrc = branch ? bw  : bh;
    const float* wrow0 = Wsrc + (long)m0 * H_;
    const float* wrow1 = Wsrc + (long)m1 * H_;

    float wa[6], wb[6];
    #pragma unroll
    for (int k = 0; k < 6; k++) wa[k] = wrow0[lane + 32 * k];
    #pragma unroll
    for (int k = 0; k < 6; k++) wb[k] = wrow1[lane + 32 * k];

    unsigned long long acc0[8], acc1[8];
    #pragma unroll
    for (int j = 0; j < 8; j++) { acc0[j] = 0ull; acc1[j] = 0ull; }

    #pragma unroll
    for (int k = 0; k < 6; k++) {
        const unsigned long long wA = pk2(wa[k], wa[k]);
        const unsigned long long wB = pk2(wb[k], wb[k]);
        const int hidx = lane + 32 * k;
        #pragma unroll
        for (int j = 0; j < 8; j++) {
            const unsigned long long pv = sp2[j][hidx];
            fma2(acc0[j], wA, pv);
            fma2(acc1[j], wB, pv);
        }
    }
    butterfly8p(acc0, lane);
    butterfly8p(acc1, lane);

    if ((lane & 3) == 0) {
        const int j  = lane >> 2;          // batch pair (j, j+8)
        const int r0 = m0 / H_, d0 = m0 - r0 * H_;
        const int r1 = m1 / H_, d1 = m1 - r1 * H_;
        const float bias0 = bsrc[m0];
        const float bias1 = bsrc[m1];
        const float2 q0 = upk2(acc0[0]);
        const float2 q1 = upk2(acc1[0]);
        const float v0a = sigmoidf_(q0.x + bias0);
        const float v0b = sigmoidf_(q0.y + bias0);
        const float v1a = sigmoidf_(q1.x + bias1);
        const float v1b = sigmoidf_(q1.y + bias1);
        if (branch == 0) {
            g_Hw[((j    ) * H_ + d0) * R_ + r0] = v0a;   // [B][H][R] fp32
            g_Hw[((j + 8) * H_ + d0) * R_ + r0] = v0b;
            g_Hw[((j    ) * H_ + d1) * R_ + r1] = v1a;
            g_Hw[((j + 8) * H_ + d1) * R_ + r1] = v1b;
        } else {
            g_Ww[((j    ) * R_ + r0) * W_ + d0] = tf32f(v0a);   // [B][R][W] tf32
            g_Ww[((j + 8) * R_ + r0) * W_ + d0] = tf32f(v0b);
            g_Ww[((j    ) * R_ + r1) * W_ + d1] = tf32f(v1a);
            g_Ww[((j + 8) * R_ + r1) * W_ + d1] = tf32f(v1b);
        }
    }
}

// ---------------- kernel 4: tensor-core main GEMM + elementwise ----------
// Block = (h-pair, b), 512 threads = 16 warps, 2 h per block (sV amortized).
// sT[r][c] CPAD=72 (no transpose: coalesced LDG.128 + conflict-free
// STS.128 fills; A-fragment LDS banks t*8+g = 0..31 distinct).
// sV[r][w] WPAD=200 (row stride 800B % 16 == 0 -> STS.128 legal;
// B-fragment banks t*8+g distinct). Grid 1536 -> 5.2 waves (was 10.4).
#define CPAD 72
#define WPAD 200
#define ST_U32  (R_ * CPAD)            // 4608 per h
#define SV_U32  (R_ * WPAD)            // 12800
#define MAIN_SMEM_BYTES ((2 * ST_U32 + SV_U32 + 2 * R_) * 4)

extern __shared__ uint32_t smem_u32[];
__global__ void __launch_bounds__(512, 2) main_tc_kernel(const float* __restrict__ X,
                                                         float* __restrict__ out) {
    const int hp = blockIdx.x;  // 0..95
    const int b  = blockIdx.y;  // 0..15
    const int h0 = hp * 2;

    uint32_t* sT0 = smem_u32;                  // [r][c] tf32, h0
    uint32_t* sT1 = smem_u32 + ST_U32;         // [r][c] tf32, h1
    uint32_t* sV  = smem_u32 + 2 * ST_U32;     // [r][w] tf32
    float*    shw = (float*)(smem_u32 + 2 * ST_U32 + SV_U32);  // [2][R]

    const int tid  = threadIdx.x;
    const int warp = tid >> 5;            // 0..15
    const int lane = tid & 31;
    const int g    = lane >> 2;           // fragment group row
    const int t    = lane & 3;            // thread in group
    const int warp_m = warp & 1;          // c half
    const int warp_n = warp >> 1;         // 0..7 -> 24-w strip

    if (tid < 2 * R_)
        shw[tid] = g_Hw[(b * H_ + h0 + (tid >> 6)) * R_ + (tid & 63)];
    __syncthreads();

    // fill sT0/sT1: coalesced float4 LDG of T, scale by hw, STS.128
    {
        const float4* Tb4 = (const float4*)(g_T + b * (R_ * C_));
        #pragma unroll
        for (int it = 0; it < 2; it++) {
            const int i4 = tid + it * 512;           // 0..1023
            const int r  = i4 >> 4;
            const int c4 = i4 & 15;
            const float4 tv = Tb4[i4];
            const float w0 = shw[r];
            const float w1 = shw[R_ + r];
            uint4 u0, u1;
            u0.x = tf32_of(tv.x * w0); u0.y = tf32_of(tv.y * w0);
            u0.z = tf32_of(tv.z * w0); u0.w = tf32_of(tv.w * w0);
            u1.x = tf32_of(tv.x * w1); u1.y = tf32_of(tv.y * w1);
            u1.z = tf32_of(tv.z * w1); u1.w = tf32_of(tv.w * w1);
            *(uint4*)(sT0 + r * CPAD + c4 * 4) = u0;
            *(uint4*)(sT1 + r * CPAD + c4 * 4) = u1;
        }
    }
    // fill sV: pure bit-copy of pre-rounded g_Ww
    {
        const uint4* Wb4 = (const uint4*)(g_Ww + b * (R_ * W_));
        #pragma unroll
        for (int it = 0; it < 6; it++) {
            const int i4 = tid + it * 512;           // 0..3071
            const int r  = i4 / 48;
            const int w4 = i4 - r * 48;
            *(uint4*)(sV + r * WPAD + w4 * 4) = Wb4[i4];
        }
    }
    __syncthreads();

    const int n0  = warp_n * 24;
    const int mt0 = 2 * warp_m;

    #pragma unroll
    for (int hi = 0; hi < 2; hi++) {
        const uint32_t* sT = hi ? sT1 : sT0;
        const int h = h0 + hi;

        float d[2][3][4];
        #pragma unroll
        for (int mi = 0; mi < 2; mi++)
            #pragma unroll
            for (int ni = 0; ni < 3; ni++)
                #pragma unroll
                for (int q = 0; q < 4; q++) d[mi][ni][q] = 0.f;

        #pragma unroll
        for (int k0 = 0; k0 < R_; k0 += 8) {
            uint32_t a[2][4];
            #pragma unroll
            for (int mi = 0; mi < 2; mi++) {
                const int col = 16 * (mt0 + mi) + g;
                a[mi][0] = sT[(k0 + t) * CPAD + col];
                a[mi][1] = sT[(k0 + t) * CPAD + col + 8];
                a[mi][2] = sT[(k0 + t + 4) * CPAD + col];
                a[mi][3] = sT[(k0 + t + 4) * CPAD + col + 8];
            }
            uint32_t bb[3][2];
            #pragma unroll
            for (int ni = 0; ni < 3; ni++) {
                const int wcol = n0 + 8 * ni + g;
                bb[ni][0] = sV[(k0 + t) * WPAD + wcol];
                bb[ni][1] = sV[(k0 + t + 4) * WPAD + wcol];
            }
            #pragma unroll
            for (int mi = 0; mi < 2; mi++)
                #pragma unroll
                for (int ni = 0; ni < 3; ni++)
                    mma_tf32(d[mi][ni], a[mi][0], a[mi][1], a[mi][2], a[mi][3],
                             bb[ni][0], bb[ni][1]);
        }

        // epilogue: c rows {16(mt0+mi)+g, +8}, w cols {n0+8ni+2t, +1}
        #pragma unroll
        for (int mi = 0; mi < 2; mi++) {
            #pragma unroll
            for (int ni = 0; ni < 3; ni++) {
                const int c0 = 16 * (mt0 + mi) + g;
                const int w  = n0 + 8 * ni + 2 * t;
                const long i0 = ((long)(b * C_ + c0) * H_ + h) * W_ + w;
                const long i1 = i0 + 8L * H_ * W_;

                const float2 x0 = *(const float2*)(X + i0);
                const float2 x1 = *(const float2*)(X + i1);
                float2 o0, o1;
                o0.x = d[mi][ni][0] * x0.x;
                o0.y = d[mi][ni][1] * x0.y;
                o1.x = d[mi][ni][2] * x1.x;
                o1.y = d[mi][ni][3] * x1.y;
                *(float2*)(out + i0) = o0;
                *(float2*)(out + i1) = o1;
            }
        }
    }
}

// ---------------- launch ---------------------------------------------------
extern "C" void kernel_launch(void* const* d_in, const int* in_sizes, int n_in,
                              void* d_out, int out_size) {
    const float* X   = (const float*)d_in[0];
    const float* p   = (const float*)d_in[1];
    const float* Wc  = (const float*)d_in[2];
    const float* bc  = (const float*)d_in[3];
    const float* Wh  = (const float*)d_in[4];
    const float* bh  = (const float*)d_in[5];
    const float* Wwp = (const float*)d_in[6];
    const float* bw  = (const float*)d_in[7];
    float* out = (float*)d_out;

    static int attr_done = 0;
    if (!attr_done) {
        cudaFuncSetAttribute(main_tc_kernel,
                             cudaFuncAttributeMaxDynamicSharedMemorySize,
                             MAIN_SMEM_BYTES);
        attr_done = 1;
    }

    pool_kernel<<<dim3(C_, B_), 192>>>(X);                               // 1
    hw_pool_kernel<<<(B_ * H_ + 255) / 256, 256>>>();                    // 2
    weights_kernel<<<dim3((R_ * H_) / 16, 3), 256>>>(Wh, bh, Wwp, bw,    // 3
                                                     Wc, bc, p);
    main_tc_kernel<<<dim3(H_ / 2, B_), 512, MAIN_SMEM_BYTES>>>(X, out);  // 4
}